// round 15
// baseline (speedup 1.0000x reference)
#include <cuda_runtime.h>

// PixelWiseNet: out[h,w] = bias + sum_{c,k} p_a[c,k]*relu(x[c,h,w]*rowsum(M[c]) + bias_c[c] - p_t[c,k])
// C=3, H=W=1024, K=16.  Output [1024,1024] f32.
//
// PWL-in-x per channel: g_c(x) = A[j]*x + B[j], j = #{r: xb_r <= x} (xb sorted).
// Sign of scale folded into table build; bias + scale==0 constants in channel-0 B.
//
// R14: two-kernel split. kernel1 (1 tiny block) builds the sorted-breakpoint +
// segment tables ONCE into __device__ globals. kernel2 is the hot loop with
// ZERO shared memory, ZERO barriers, ZERO prologue — tables via __ldg (L1-hot
// after first touch). 128-thread blocks, grid 2048, ~8192 warps.

#define C 3
#define K 16
#define HW (1024 * 1024)
#define N4 (HW / 4)
#define THREADS 128
#define BLOCKS (N4 / THREADS)    // 2048

// ---- device-global tables built by prep kernel ----
__device__ __align__(16) float g_sxb[C * K];     // sorted breakpoints (quartile-readable)
__device__ __align__(16) float2 g_AB[C * 17];    // segment coefficients
__device__ __align__(16) float g_piv[12];        // [c*4+{0,1,2}] level-1 pivots

__global__ void prep_kernel(const float* __restrict__ M,
                            const float* __restrict__ p_a,
                            const float* __restrict__ p_t,
                            const float* __restrict__ bias_c,
                            const float* __restrict__ bias) {
    __shared__ float sh_xb[C * K];
    __shared__ float sh_s[C * K];
    __shared__ float sh_cst[C * K];
    __shared__ float sh_sxb[C * K];
    __shared__ float sh_ss[C * K];
    __shared__ float sh_scale[C];
    __shared__ float sh_const;

    const int tid = threadIdx.x;   // 64 threads

    // stage 1: transform
    if (tid < C * K) {
        int c = tid / K;
        float scale = M[c * 3 + 0] + M[c * 3 + 1] + M[c * 3 + 2];
        float a = p_a[tid], t = p_t[tid], bc = bias_c[c];
        float xb, s, cst;
        if (scale != 0.0f) {
            xb  = (t - bc) / scale;
            s   = a * scale;
            cst = 0.0f;
        } else {
            xb = 0.0f; s = 0.0f;
            cst = a * fmaxf(bc - t, 0.0f);
        }
        sh_xb[tid]  = xb;
        sh_s[tid]   = s;
        sh_cst[tid] = cst;
        if (tid < C) sh_scale[tid] = scale;
    }
    __syncthreads();

    // stage 2: rank sort per channel + CONST
    if (tid < C * K) {
        int c = tid / K, k = tid % K;
        float my = sh_xb[tid];
        int rank = 0;
        #pragma unroll
        for (int j = 0; j < K; j++) {
            float o = sh_xb[c * K + j];
            rank += (o < my || (o == my && j < k)) ? 1 : 0;
        }
        sh_sxb[c * K + rank] = my;
        sh_ss[c * K + rank]  = sh_s[tid];
    } else if (tid == C * K) {
        float v = bias[0];
        #pragma unroll
        for (int r = 0; r < C * K; r++) v += sh_cst[r];
        sh_const = v;
    }
    __syncthreads();

    // stage 3: tables -> globals
    if (tid < C * 17) {
        int c = tid / 17, j = tid % 17;
        bool pos = (sh_scale[c] >= 0.0f);
        float A = 0.0f, B = 0.0f;
        #pragma unroll
        for (int r = 0; r < K; r++) {
            float sv = sh_ss[c * K + r];
            float xv = sh_sxb[c * K + r];
            bool take = pos ? (r < j) : (r >= j);
            if (take) { A += sv; B -= sv * xv; }
        }
        if (c == 0) B += sh_const;
        g_AB[tid] = make_float2(A, B);
    }
    if (tid < C * K) g_sxb[tid] = sh_sxb[tid];
    if (tid < C) {
        g_piv[tid * 4 + 0] = sh_sxb[tid * K + 3];
        g_piv[tid * 4 + 1] = sh_sxb[tid * K + 7];
        g_piv[tid * 4 + 2] = sh_sxb[tid * K + 11];
        g_piv[tid * 4 + 3] = 0.0f;
    }
}

__global__ __launch_bounds__(THREADS)
void pixelwise_kernel(const float4* __restrict__ x,
                      float4* __restrict__ out) {
    const int i = blockIdx.x * THREADS + threadIdx.x;

    // x loads first: 3 LDG.128 in flight while pivots/tables load
    const float4 v0 = x[i];
    const float4 v1 = x[N4 + i];
    const float4 v2 = x[2 * N4 + i];

    // uniform pivot loads (broadcast, L1-hot after first touch per SM)
    const float4 pv0 = __ldg((const float4*)&g_piv[0]);
    const float4 pv1 = __ldg((const float4*)&g_piv[4]);
    const float4 pv2 = __ldg((const float4*)&g_piv[8]);

    const float4* __restrict__ st4 = (const float4*)g_sxb;   // [C*4] quartiles
    const float2* __restrict__ ab  = g_AB;

    float xs[C][4];
    xs[0][0]=v0.x; xs[0][1]=v0.y; xs[0][2]=v0.z; xs[0][3]=v0.w;
    xs[1][0]=v1.x; xs[1][1]=v1.y; xs[1][2]=v1.z; xs[1][3]=v1.w;
    xs[2][0]=v2.x; xs[2][1]=v2.y; xs[2][2]=v2.z; xs[2][3]=v2.w;

    const float pA[C] = {pv0.x, pv1.x, pv2.x};
    const float pB[C] = {pv0.y, pv1.y, pv2.y};
    const float pC[C] = {pv0.z, pv1.z, pv2.z};

    float accA[4] = {0.f,0.f,0.f,0.f};
    float accB[4] = {0.f,0.f,0.f,0.f};

    #pragma unroll
    for (int c = 0; c < C; c++) {
        const float p0 = pA[c], p1 = pB[c], p2 = pC[c];
        #pragma unroll
        for (int p = 0; p < 4; p++) {
            float u = xs[c][p];
            int m = (u >= p0) + (u >= p1) + (u >= p2);
            float4 q = __ldg(&st4[c * 4 + m]);
            int j = m * 4 + (u >= q.x) + (u >= q.y) + (u >= q.z) + (u >= q.w);
            float2 AB = __ldg(&ab[c * 17 + j]);
            accA[p] = fmaf(u, AB.x, accA[p]);
            accB[p] += AB.y;
        }
    }

    out[i] = make_float4(accA[0] + accB[0], accA[1] + accB[1],
                         accA[2] + accB[2], accA[3] + accB[3]);
}

extern "C" void kernel_launch(void* const* d_in, const int* in_sizes, int n_in,
                              void* d_out, int out_size) {
    const float4* x      = (const float4*)d_in[0];
    const float*  M      = (const float*)d_in[1];
    const float*  p_a    = (const float*)d_in[2];
    const float*  p_t    = (const float*)d_in[3];
    const float*  bias_c = (const float*)d_in[4];
    const float*  bias   = (const float*)d_in[5];
    float4* out = (float4*)d_out;

    prep_kernel<<<1, 64>>>(M, p_a, p_t, bias_c, bias);
    pixelwise_kernel<<<BLOCKS, THREADS>>>(x, out);
}

// round 17
// speedup vs baseline: 1.2587x; 1.2587x over previous
#include <cuda_runtime.h>

// PixelWiseNet: out[h,w] = bias + sum_{c,k} p_a[c,k]*relu(x[c,h,w]*rowsum(M[c]) + bias_c[c] - p_t[c,k])
// C=3, H=W=1024, K=16.  Output [1024,1024] f32.
//
// PWL-in-x per channel: g_c(x) = A[j]*x + B[j], j = #{r: xb_r <= x} (xb sorted).
// Sign of scale folded into table build; bias + scale==0 constants in channel-0 B.
// Hot loop per value: 3 reg-pivot compares -> LDS.128 quartile -> 4 compares ->
// LDS.64 (A,B) -> FFMA + FADD.
//
// R15: R8 (best, ncu 9.12) with the grid-balance defect fixed: 128-thread
// blocks, grid 1024 (6.9 blocks/SM, wave-tail 7% instead of 15%), same
// 8 px/thread, same hoisted LDGs over the smem prologue, single kernel.

#define C 3
#define K 16
#define HW (1024 * 1024)
#define N4 (HW / 4)
#define THREADS 128
#define PXT 2                           // float4 per plane per thread
#define BLOCKS (N4 / (THREADS * PXT))   // 1024

__global__ __launch_bounds__(THREADS, 8)
void pixelwise_kernel(const float4* __restrict__ x,
                      const float* __restrict__ M,
                      const float* __restrict__ p_a,
                      const float* __restrict__ p_t,
                      const float* __restrict__ bias_c,
                      const float* __restrict__ bias,
                      float4* __restrict__ out) {
    __shared__ __align__(16) float sh_sxb[C * K];  // sorted breakpoints
    __shared__ float  sh_ss[C * K];                // slopes, sorted order
    __shared__ float  sh_xb[C * K];                // scratch: unsorted breakpoints
    __shared__ float  sh_s[C * K];                 // scratch: unsorted slopes
    __shared__ float  sh_cst[C * K];               // scale==0 constants
    __shared__ float2 sh_AB[C * 17];               // (A_j, B_j)
    __shared__ float  sh_scale[C];
    __shared__ float  sh_const;

    const int tid = threadIdx.x;
    const int i = blockIdx.x * (THREADS * PXT) + tid;

    // ---- issue all 6 LDG.128 FIRST: in flight during the prologue ----
    const float4 v0a = x[i];
    const float4 v0b = x[i + THREADS];
    const float4 v1a = x[N4 + i];
    const float4 v1b = x[N4 + i + THREADS];
    const float4 v2a = x[2 * N4 + i];
    const float4 v2b = x[2 * N4 + i + THREADS];

    // ---- stage 1: transform (48 lanes) ----
    if (tid < C * K) {
        int c = tid / K;
        float scale = M[c * 3 + 0] + M[c * 3 + 1] + M[c * 3 + 2];
        float a = p_a[tid], t = p_t[tid], bc = bias_c[c];
        float xb, s, cst;
        if (scale != 0.0f) {
            xb  = (t - bc) / scale;
            s   = a * scale;
            cst = 0.0f;
        } else {
            xb = 0.0f; s = 0.0f;
            cst = a * fmaxf(bc - t, 0.0f);
        }
        sh_xb[tid]  = xb;
        sh_s[tid]   = s;
        sh_cst[tid] = cst;
        if (tid < C) sh_scale[tid] = scale;
    }
    __syncthreads();

    // ---- stage 2: rank sort per channel (48 lanes) + CONST (lane 48) ----
    if (tid < C * K) {
        int c = tid / K, k = tid % K;
        float my = sh_xb[tid];
        int rank = 0;
        #pragma unroll
        for (int j = 0; j < K; j++) {
            float o = sh_xb[c * K + j];
            rank += (o < my || (o == my && j < k)) ? 1 : 0;
        }
        sh_sxb[c * K + rank] = my;
        sh_ss[c * K + rank]  = sh_s[tid];
    } else if (tid == C * K) {
        float v = bias[0];
        #pragma unroll
        for (int r = 0; r < C * K; r++) v += sh_cst[r];
        sh_const = v;
    }
    __syncthreads();

    // ---- stage 3: segment tables (51 lanes) ----
    if (tid < C * 17) {
        int c = tid / 17, j = tid % 17;
        bool pos = (sh_scale[c] >= 0.0f);
        float A = 0.0f, B = 0.0f;
        #pragma unroll
        for (int r = 0; r < K; r++) {
            float sv = sh_ss[c * K + r];
            float xv = sh_sxb[c * K + r];
            bool take = pos ? (r < j) : (r >= j);
            if (take) { A += sv; B -= sv * xv; }
        }
        if (c == 0) B += sh_const;
        sh_AB[tid] = make_float2(A, B);
    }
    __syncthreads();

    // ---- main: 8 pixels per thread ----
    const float4* st4 = (const float4*)sh_sxb;

    float xs[C][8];
    xs[0][0]=v0a.x; xs[0][1]=v0a.y; xs[0][2]=v0a.z; xs[0][3]=v0a.w;
    xs[0][4]=v0b.x; xs[0][5]=v0b.y; xs[0][6]=v0b.z; xs[0][7]=v0b.w;
    xs[1][0]=v1a.x; xs[1][1]=v1a.y; xs[1][2]=v1a.z; xs[1][3]=v1a.w;
    xs[1][4]=v1b.x; xs[1][5]=v1b.y; xs[1][6]=v1b.z; xs[1][7]=v1b.w;
    xs[2][0]=v2a.x; xs[2][1]=v2a.y; xs[2][2]=v2a.z; xs[2][3]=v2a.w;
    xs[2][4]=v2b.x; xs[2][5]=v2b.y; xs[2][6]=v2b.z; xs[2][7]=v2b.w;

    float acc[8] = {0.f,0.f,0.f,0.f,0.f,0.f,0.f,0.f};

    #pragma unroll
    for (int c = 0; c < C; c++) {
        // block-uniform pivots -> registers (broadcast LDS)
        const float p0 = sh_sxb[c * K + 3];
        const float p1 = sh_sxb[c * K + 7];
        const float p2 = sh_sxb[c * K + 11];
        const float2* ab = &sh_AB[c * 17];

        #pragma unroll
        for (int p = 0; p < 8; p++) {
            float u = xs[c][p];
            int m = (u >= p0) + (u >= p1) + (u >= p2);
            float4 q = st4[c * 4 + m];
            int j = m * 4 + (u >= q.x) + (u >= q.y) + (u >= q.z) + (u >= q.w);
            float2 AB = ab[j];
            acc[p] = fmaf(u, AB.x, acc[p]);
            acc[p] += AB.y;
        }
    }

    out[i]           = make_float4(acc[0], acc[1], acc[2], acc[3]);
    out[i + THREADS] = make_float4(acc[4], acc[5], acc[6], acc[7]);
}

extern "C" void kernel_launch(void* const* d_in, const int* in_sizes, int n_in,
                              void* d_out, int out_size) {
    const float4* x      = (const float4*)d_in[0];
    const float*  M      = (const float*)d_in[1];
    const float*  p_a    = (const float*)d_in[2];
    const float*  p_t    = (const float*)d_in[3];
    const float*  bias_c = (const float*)d_in[4];
    const float*  bias   = (const float*)d_in[5];
    float4* out = (float4*)d_out;

    pixelwise_kernel<<<BLOCKS, THREADS>>>(x, M, p_a, p_t, bias_c, bias, out);
}